// round 2
// baseline (speedup 1.0000x reference)
#include <cuda_runtime.h>
#include <math.h>

#define DIM 1024
#define ROWS_PER_BLOCK 8
#define NTHREADS 256

// Integer LayerNorm, one warp per row (D=1024), single pass over x.
// Row cached in registers as packed int16x2 (values |x| << 32768, exact).
// sum_sq of centered values via sumsq_x - 2*mean*sum + D*mean^2 (exact).
__global__ __launch_bounds__(NTHREADS, 6)
void iln_kernel(const float* __restrict__ x,
                const float* __restrict__ weight,
                const float* __restrict__ bias,
                float* __restrict__ out,
                int n_rows)
{
    __shared__ int s_w[DIM];
    __shared__ int s_b[DIM];
    __shared__ int s_lut[32];

    const int tid = threadIdx.x;

    // Recompute 32-entry isqrt LUT exactly: round((1<<15)/sqrt(2^parity*(1+m/16)))
    if (tid < 32) {
        const int parity = tid >> 4;
        const int mant = tid & 15;
        const double val = (double)(1 << parity) * (1.0 + (double)mant * 0.0625);
        s_lut[tid] = (int)llrint(32768.0 / sqrt(val));
    }
    // Quantize weight/bias once per block (round-half-even matches jnp.round)
    for (int i = tid; i < DIM; i += NTHREADS) {
        s_w[i] = __float2int_rn(weight[i] * 256.0f);
        s_b[i] = __float2int_rn(bias[i] * 256.0f);
    }
    __syncthreads();

    const int warp = tid >> 5;
    const int lane = tid & 31;
    const int row = blockIdx.x * ROWS_PER_BLOCK + warp;
    if (row >= n_rows) return;

    const float4* __restrict__ xr = (const float4*)(x + (size_t)row * DIM);
    float4* __restrict__ orow = (float4*)(out + (size_t)row * DIM);

    int pk[16];            // 32 int16 values packed 2-per-reg
    int sum = 0;
    int sumsq = 0;         // max ~1e8 << 2^31, exact in int32

    #pragma unroll
    for (int h = 0; h < 2; h++) {
        float4 v[4];
        #pragma unroll
        for (int j = 0; j < 4; j++)
            v[j] = xr[(h * 4 + j) * 32 + lane];
        #pragma unroll
        for (int j = 0; j < 4; j++) {
            const int a = __float2int_rn(v[j].x);
            const int b = __float2int_rn(v[j].y);
            const int c = __float2int_rn(v[j].z);
            const int d = __float2int_rn(v[j].w);
            pk[h * 8 + j * 2 + 0] = (a & 0xffff) | (b << 16);
            pk[h * 8 + j * 2 + 1] = (c & 0xffff) | (d << 16);
            sum   += a + b + c + d;
            sumsq += a * a + b * b + c * c + d * d;
        }
    }

    // Single-instruction warp reductions (REDUX.SUM)
    sum   = __reduce_add_sync(0xffffffffu, sum);
    sumsq = __reduce_add_sync(0xffffffffu, sumsq);

    // Fixed-point mean: (sum * 64) >> 16, arithmetic shift
    const int mean = (sum * 64) >> 16;
    // Exact centered sum of squares
    const long long ssy = (long long)sumsq
                        - 2LL * (long long)mean * (long long)sum
                        + (long long)DIM * (long long)mean * (long long)mean;
    long long var = (ssy * 64) >> 16;
    if (var < 1) var = 1;

    // k = floor(log2(var)) via MSB position (exact for integers)
    const int k = 63 - __clzll((unsigned long long)var);
    const int parity = k & 1;
    const int sa = k - 4;
    const int mant = (sa >= 0) ? (int)((var >> sa) & 15)
                               : (int)((var << (-sa)) & 15);
    const int inv = s_lut[(parity << 4) | mant];
    const int ts = (k >> 1) + 15;   // p + SHIFT(0) + Q_LUT(15)

    #pragma unroll
    for (int j = 0; j < 8; j++) {
        const int col = j * 128 + lane * 4;
        const int p0 = pk[j * 2 + 0];
        const int p1 = pk[j * 2 + 1];
        const int a = (p0 << 16) >> 16;   // arithmetic unpack (exact)
        const int b =  p0 >> 16;
        const int c = (p1 << 16) >> 16;
        const int d =  p1 >> 16;
        float4 o;
        long long t;
        t = (((long long)((a - mean) * inv) * (long long)s_w[col + 0]) >> ts) + s_b[col + 0];
        o.x = (float)t * 0.00390625f;
        t = (((long long)((b - mean) * inv) * (long long)s_w[col + 1]) >> ts) + s_b[col + 1];
        o.y = (float)t * 0.00390625f;
        t = (((long long)((c - mean) * inv) * (long long)s_w[col + 2]) >> ts) + s_b[col + 2];
        o.z = (float)t * 0.00390625f;
        t = (((long long)((d - mean) * inv) * (long long)s_w[col + 3]) >> ts) + s_b[col + 3];
        o.w = (float)t * 0.00390625f;
        orow[j * 32 + lane] = o;
    }
}

extern "C" void kernel_launch(void* const* d_in, const int* in_sizes, int n_in,
                              void* d_out, int out_size) {
    const float* x      = (const float*)d_in[0];
    const float* weight = (const float*)d_in[1];
    const float* bias   = (const float*)d_in[2];
    // d_in[3] (isqrt_lut) intentionally unused: LUT recomputed exactly in-kernel.
    float* out = (float*)d_out;

    const int n_rows = in_sizes[0] / DIM;
    const int blocks = (n_rows + ROWS_PER_BLOCK - 1) / ROWS_PER_BLOCK;
    iln_kernel<<<blocks, NTHREADS>>>(x, weight, bias, out, n_rows);
}